// round 9
// baseline (speedup 1.0000x reference)
#include <cuda_runtime.h>
#include <cuda_bf16.h>
#include <cstdint>

// Problem: B=4, S=4096, H=16, Dk=Dv=64.  out = 0.95*M + sum_rows w*k v^T per head.
#define H_    16
#define DK_   64
#define DV_   64
#define HD_   1024            // floats per (b,s) row = H*64
#define DECAY_ 0.95f
#define NBLK_ 444             // 148*3 -> exactly one wave at occupancy 3

// bf16x2 plane layout per buffer (u32 words): plane[kp*72 + col], kp=0..31, col=0..63.
// Stride 72 => fragment LDS banks (8c2+r2)%32 conflict-free.
#define KHI_  0
#define KLO_  2304
#define VHI_  4608
#define VLO_  6912
#define BUFW_ 9216            // u32 words per buffer (36864 B); x2 buffers = 73728 B

__device__ float g_l1w_scratch[NBLK_ * 4096];

// hi = bf16x2{lo-half=bf16(x0), hi-half=bf16(x1)}; lo = bf16x2 of residuals
__device__ __forceinline__ void split2(float x0, float x1, uint32_t& hi, uint32_t& lo) {
    asm("cvt.rn.bf16x2.f32 %0, %1, %2;" : "=r"(hi) : "f"(x1), "f"(x0));
    float h0 = __uint_as_float(hi << 16);
    float h1 = __uint_as_float(hi & 0xffff0000u);
    float l0 = x0 - h0;
    float l1 = x1 - h1;
    asm("cvt.rn.bf16x2.f32 %0, %1, %2;" : "=r"(lo) : "f"(l1), "f"(l0));
}

__device__ __forceinline__ void mma16816(float* c, const uint32_t* a,
                                         uint32_t b0, uint32_t b1) {
    asm volatile(
        "mma.sync.aligned.m16n8k16.row.col.f32.bf16.bf16.f32 "
        "{%0,%1,%2,%3}, {%4,%5,%6,%7}, {%8,%9}, {%0,%1,%2,%3};"
        : "+f"(c[0]), "+f"(c[1]), "+f"(c[2]), "+f"(c[3])
        : "r"(a[0]), "r"(a[1]), "r"(a[2]), "r"(a[3]), "r"(b0), "r"(b1));
}

// ---- stage load: all 16 LDG.128 (+w) for one 64-row stage into registers ----
#define LOAD_STAGE(stg)                                                        \
    do {                                                                       \
        const int row0_ = (stg) * 64;                                          \
        _Pragma("unroll")                                                      \
        for (int it = 0; it < 8; ++it) {                                       \
            const int kp = it * 4 + wid;                                       \
            const int r0 = row0_ + 2 * kp;                                     \
            const float* mp = mat + (size_t)r0 * HD_ + 4 * q;                  \
            a0[it] = *(const float4*)mp;                                       \
            a1[it] = *(const float4*)(mp + HD_);                               \
            if (vlane) wv[it] = *(const float2*)(ws + r0);                     \
        }                                                                      \
    } while (0)

// ---- stage convert+store into buffer `sel` ----
#define STORE_STAGE(sel)                                                       \
    do {                                                                       \
        uint32_t* pl = dsm + (sel) * BUFW_;                                    \
        _Pragma("unroll")                                                      \
        for (int it = 0; it < 8; ++it) {                                       \
            const int kp = it * 4 + wid;                                       \
            float4 A = a0[it], B = a1[it];                                     \
            if (vlane) {                                                       \
                A.x *= wv[it].x; A.y *= wv[it].x;                              \
                A.z *= wv[it].x; A.w *= wv[it].x;                              \
                B.x *= wv[it].y; B.y *= wv[it].y;                              \
                B.z *= wv[it].y; B.w *= wv[it].y;                              \
            }                                                                  \
            uint32_t h0, l0, h1, l1, h2, l2, h3, l3;                           \
            split2(A.x, B.x, h0, l0);                                          \
            split2(A.y, B.y, h1, l1);                                          \
            split2(A.z, B.z, h2, l2);                                          \
            split2(A.w, B.w, h3, l3);                                          \
            const uint32_t wb = (uint32_t)(kp * 72 + 4 * q);                   \
            *(uint4*)(pl + baseHi + wb) = make_uint4(h0, h1, h2, h3);          \
            *(uint4*)(pl + baseLo + wb) = make_uint4(l0, l1, l2, l3);          \
        }                                                                      \
    } while (0)

__global__ __launch_bounds__(128, 3)
void l1w_hmma_kernel(const float* __restrict__ keys,
                     const float* __restrict__ values,
                     const float* __restrict__ ws) {
    extern __shared__ __align__(16) uint32_t dsm[];

    const int tid  = threadIdx.x;
    const int wid  = tid >> 5;
    const int lane = tid & 31;
    const int bid  = blockIdx.x;

    // bid -> (head h, first stage s0, stage count nt); 256 stages of 64 rows per head.
    int h, nt, s0;
    if (bid < 336) {                       // heads 0..11: 28 chunks each
        h = bid / 28;
        const int ci = bid - 28 * h;
        if (ci < 4) { nt = 10; s0 = 10 * ci; }
        else        { nt = 9;  s0 = 40 + 9 * (ci - 4); }
    } else {                               // heads 12..15: 27 chunks each
        const int r = bid - 336;
        h = 12 + r / 27;
        const int ci = r - 27 * (h - 12);
        if (ci < 13) { nt = 10; s0 = 10 * ci; }
        else         { nt = 9;  s0 = 130 + 9 * (ci - 13); }
    }

    const bool vlane = (lane >= 16);
    const int  q     = lane & 15;
    const float* mat = (vlane ? values : keys) + (size_t)h * DK_;
    const uint32_t baseHi = vlane ? VHI_ : KHI_;
    const uint32_t baseLo = baseHi + 2304u;

    float cacc[4][2][4];
#pragma unroll
    for (int mt = 0; mt < 4; ++mt)
#pragma unroll
        for (int n2 = 0; n2 < 2; ++n2)
#pragma unroll
            for (int i = 0; i < 4; ++i) cacc[mt][n2][i] = 0.0f;

    float4 a0[8], a1[8];
    float2 wv[8];

    // prologue: stage 0 -> buffer 0
    LOAD_STAGE(s0);
    STORE_STAGE(0);
    __syncthreads();

    const int r2 = lane >> 2;
    const int c2 = lane & 3;
    const int nb = wid * 16;

    for (int s = 0; s < nt; ++s) {
        if (s + 1 < nt) LOAD_STAGE(s0 + s + 1);   // LDGs in flight under the MMAs

        // ---- compute from buffer s&1 ----
        {
            const uint32_t* sm = dsm + (s & 1) * BUFW_;
#pragma unroll
            for (int st = 0; st < 4; ++st) {
                const uint32_t krow = (uint32_t)((8 * st + c2) * 72);
                uint32_t bH[2][2], bL[2][2];
#pragma unroll
                for (int n2 = 0; n2 < 2; ++n2) {
                    const uint32_t nn = (uint32_t)(nb + 8 * n2 + r2);
                    bH[n2][0] = sm[VHI_ + krow + nn];
                    bH[n2][1] = sm[VHI_ + krow + 288 + nn];
                    bL[n2][0] = sm[VLO_ + krow + nn];
                    bL[n2][1] = sm[VLO_ + krow + 288 + nn];
                }
#pragma unroll
                for (int mt = 0; mt < 4; ++mt) {
                    const uint32_t cc = (uint32_t)(16 * mt + r2);
                    uint32_t aH[4], aL[4];
                    aH[0] = sm[KHI_ + krow + cc];
                    aH[1] = sm[KHI_ + krow + cc + 8];
                    aH[2] = sm[KHI_ + krow + 288 + cc];
                    aH[3] = sm[KHI_ + krow + 288 + cc + 8];
                    aL[0] = sm[KLO_ + krow + cc];
                    aL[1] = sm[KLO_ + krow + cc + 8];
                    aL[2] = sm[KLO_ + krow + 288 + cc];
                    aL[3] = sm[KLO_ + krow + 288 + cc + 8];
#pragma unroll
                    for (int n2 = 0; n2 < 2; ++n2) {
                        mma16816(cacc[mt][n2], aH, bH[n2][0], bH[n2][1]);
                        mma16816(cacc[mt][n2], aH, bL[n2][0], bL[n2][1]);
                        mma16816(cacc[mt][n2], aL, bH[n2][0], bH[n2][1]);
                    }
                }
            }
        }

        if (s + 1 < nt) {
            STORE_STAGE((s + 1) & 1);
            __syncthreads();
        }
    }

    // ---- epilogue: per-warp 64x16 partial tile -> scratch[bid] ----
    float* outp = g_l1w_scratch + (size_t)bid * 4096;
#pragma unroll
    for (int mt = 0; mt < 4; ++mt)
#pragma unroll
        for (int n2 = 0; n2 < 2; ++n2) {
            const int row = 16 * mt + (lane >> 2);
            const int col = wid * 16 + 8 * n2 + 2 * (lane & 3);
            *(float2*)(outp + (size_t)row * DV_ + col) =
                make_float2(cacc[mt][n2][0], cacc[mt][n2][1]);
            *(float2*)(outp + (size_t)(row + 8) * DV_ + col) =
                make_float2(cacc[mt][n2][2], cacc[mt][n2][3]);
        }
}

__global__ void l1w_reduce_kernel(const float* __restrict__ memory,
                                  float* __restrict__ out) {
    const int e = blockIdx.x * blockDim.x + threadIdx.x;   // 0..65535
    const int h = e >> 12;
    const int inner = e & 4095;
    const int base = (h < 12) ? 28 * h : 336 + 27 * (h - 12);
    float s = 0.0f;
#pragma unroll
    for (int i = 0; i < 27; ++i)
        s += g_l1w_scratch[(size_t)(base + i) * 4096 + inner];
    if (h < 12)
        s += g_l1w_scratch[(size_t)(base + 27) * 4096 + inner];
    out[e] = DECAY_ * memory[e] + s;
}

extern "C" void kernel_launch(void* const* d_in, const int* in_sizes, int n_in,
                              void* d_out, int out_size) {
    const float* memory = (const float*)d_in[0];   // (16,64,64)
    const float* keys   = (const float*)d_in[1];   // (4,4096,16,64)
    const float* values = (const float*)d_in[2];   // (4,4096,16,64)
    const float* ws     = (const float*)d_in[3];   // (4,4096)
    float* out = (float*)d_out;                    // (16,64,64)

    static bool attr_set = false;
    if (!attr_set) {
        cudaFuncSetAttribute(l1w_hmma_kernel,
                             cudaFuncAttributeMaxDynamicSharedMemorySize,
                             2 * BUFW_ * 4);
        attr_set = true;
    }

    l1w_hmma_kernel<<<NBLK_, 128, 2 * BUFW_ * 4>>>(keys, values, ws);
    l1w_reduce_kernel<<<512, 128>>>(memory, out);
}

// round 10
// speedup vs baseline: 1.2262x; 1.2262x over previous
#include <cuda_runtime.h>
#include <cstdint>

// Problem: B=4, S=4096, H=16, Dk=Dv=64.  out = 0.95*M + sum_rows w*k v^T per head.
#define H_     16
#define DK_    64
#define DV_    64
#define HD_    1024           // floats per (b,s) row = H*64
#define DECAY_ 0.95f
#define NBLK_  444            // 148*3 -> exactly one wave at occupancy 3

// Raw fp32 smem planes per buffer: K[k][m], V[k][n], k=0..63, row stride 68 floats.
// Bank of element (k,m) = (4k + m) % 32 -> fragment LDS conflict-free (8c2+r2 distinct).
#define KSTR_   68
#define PLANEF_ (64 * KSTR_)        // 4352 floats
#define BUFF_   (2 * PLANEF_ + 64)  // + 64 w floats = 8768 floats
#define BUFB_   35072               // bytes per buffer
#define VOFF_B_ 17408               // V plane byte offset
#define WOFF_B_ 34816               // w byte offset

// hi = bf16x2{lo-half=bf16(x0), hi-half=bf16(x1)}; lo = bf16x2 of residuals
__device__ __forceinline__ void split2(float x0, float x1, uint32_t& hi, uint32_t& lo) {
    asm("cvt.rn.bf16x2.f32 %0, %1, %2;" : "=r"(hi) : "f"(x1), "f"(x0));
    float h0 = __uint_as_float(hi << 16);
    float h1 = __uint_as_float(hi & 0xffff0000u);
    float l0 = x0 - h0;
    float l1 = x1 - h1;
    asm("cvt.rn.bf16x2.f32 %0, %1, %2;" : "=r"(lo) : "f"(l1), "f"(l0));
}

__device__ __forceinline__ void mma16816(float* c, const uint32_t* a,
                                         uint32_t b0, uint32_t b1) {
    asm volatile(
        "mma.sync.aligned.m16n8k16.row.col.f32.bf16.bf16.f32 "
        "{%0,%1,%2,%3}, {%4,%5,%6,%7}, {%8,%9}, {%0,%1,%2,%3};"
        : "+f"(c[0]), "+f"(c[1]), "+f"(c[2]), "+f"(c[3])
        : "r"(a[0]), "r"(a[1]), "r"(a[2]), "r"(a[3]), "r"(b0), "r"(b1));
}

__device__ __forceinline__ void cp16(uint32_t dst, const float* src) {
    asm volatile("cp.async.cg.shared.global [%0], [%1], 16;" :: "r"(dst), "l"(src));
}

// Issue all cp.asyncs for one 64-row stage into buffer b, then commit the group.
#define ISSUE_STAGE(stg, b)                                                    \
    do {                                                                       \
        const int row0_ = (stg) * 64;                                          \
        const uint32_t bb_ = sbase + (uint32_t)(b) * BUFB_;                    \
        _Pragma("unroll")                                                      \
        for (int i = 0; i < 8; ++i) {                                          \
            const int idx = i * 128 + tid;                                     \
            const int row = idx >> 4;                                          \
            const int seg = idx & 15;                                          \
            const uint32_t d = (uint32_t)(row * 272 + seg * 16);               \
            const size_t g = (size_t)(row0_ + row) * HD_ + seg * 4;            \
            cp16(bb_ + d, kbase + g);                                          \
            cp16(bb_ + VOFF_B_ + d, vbase + g);                                \
        }                                                                      \
        if (tid < 16) cp16(bb_ + WOFF_B_ + tid * 16, ws + row0_ + tid * 4);    \
        asm volatile("cp.async.commit_group;" ::: "memory");                   \
    } while (0)

__global__ __launch_bounds__(128, 3)
void l1w_main_kernel(const float* __restrict__ keys,
                     const float* __restrict__ values,
                     const float* __restrict__ ws,
                     float* __restrict__ out) {
    extern __shared__ __align__(16) float dsm[];
    uint32_t sbase;
    asm("{ .reg .u64 t; cvta.to.shared.u64 t, %1; cvt.u32.u64 %0, t; }"
        : "=r"(sbase) : "l"(dsm));

    const int tid  = threadIdx.x;
    const int wid  = tid >> 5;
    const int lane = tid & 31;
    const int bid  = blockIdx.x;

    // bid -> (head h, first stage s0, stage count nt); 256 stages of 64 rows per head.
    int h, nt, s0;
    if (bid < 336) {                       // heads 0..11: 28 chunks each
        h = bid / 28;
        const int ci = bid - 28 * h;
        if (ci < 4) { nt = 10; s0 = 10 * ci; }
        else        { nt = 9;  s0 = 40 + 9 * (ci - 4); }
    } else {                               // heads 12..15: 27 chunks each
        const int r = bid - 336;
        h = 12 + r / 27;
        const int ci = r - 27 * (h - 12);
        if (ci < 13) { nt = 10; s0 = 10 * ci; }
        else         { nt = 9;  s0 = 130 + 9 * (ci - 13); }
    }

    const float* kbase = keys   + (size_t)h * DK_;
    const float* vbase = values + (size_t)h * DV_;

    const int r2 = lane >> 2;
    const int c2 = lane & 3;
    const int nb = wid * 16;

    float cacc[4][2][4];
#pragma unroll
    for (int mt = 0; mt < 4; ++mt)
#pragma unroll
        for (int n2 = 0; n2 < 2; ++n2)
#pragma unroll
            for (int i = 0; i < 4; ++i) cacc[mt][n2][i] = 0.0f;

    ISSUE_STAGE(s0, 0);

    for (int s = 0; s < nt; ++s) {
        if (s + 1 < nt) {
            ISSUE_STAGE(s0 + s + 1, (s + 1) & 1);
            asm volatile("cp.async.wait_group 1;" ::: "memory");
        } else {
            asm volatile("cp.async.wait_group 0;" ::: "memory");
        }
        __syncthreads();                         // stage s visible to all warps

        const float* Kp = dsm + (s & 1) * BUFF_;
        const float* Vp = Kp + PLANEF_;
        const float* Wp = Vp + PLANEF_;

#pragma unroll
        for (int st = 0; st < 4; ++st) {
            const int k0 = 16 * st + 2 * c2;
            const float w00 = Wp[k0],     w01 = Wp[k0 + 1];
            const float w10 = Wp[k0 + 8], w11 = Wp[k0 + 9];

            uint32_t bH[2][2], bL[2][2];
#pragma unroll
            for (int n2 = 0; n2 < 2; ++n2) {
                const int n = nb + 8 * n2 + r2;
                split2(Vp[k0 * KSTR_ + n] * w00,
                       Vp[(k0 + 1) * KSTR_ + n] * w01, bH[n2][0], bL[n2][0]);
                split2(Vp[(k0 + 8) * KSTR_ + n] * w10,
                       Vp[(k0 + 9) * KSTR_ + n] * w11, bH[n2][1], bL[n2][1]);
            }
#pragma unroll
            for (int mt = 0; mt < 4; ++mt) {
                const int m = 16 * mt + r2;
                uint32_t aH[4], aL[4];
                split2(Kp[k0 * KSTR_ + m],
                       Kp[(k0 + 1) * KSTR_ + m],     aH[0], aL[0]);
                split2(Kp[k0 * KSTR_ + m + 8],
                       Kp[(k0 + 1) * KSTR_ + m + 8], aH[1], aL[1]);
                split2(Kp[(k0 + 8) * KSTR_ + m],
                       Kp[(k0 + 9) * KSTR_ + m],     aH[2], aL[2]);
                split2(Kp[(k0 + 8) * KSTR_ + m + 8],
                       Kp[(k0 + 9) * KSTR_ + m + 8], aH[3], aL[3]);
#pragma unroll
                for (int n2 = 0; n2 < 2; ++n2) {
                    mma16816(cacc[mt][n2], aH, bH[n2][0], bH[n2][1]);
                    mma16816(cacc[mt][n2], aH, bL[n2][0], bL[n2][1]);
                    mma16816(cacc[mt][n2], aL, bH[n2][0], bH[n2][1]);
                }
            }
        }
        __syncthreads();                         // buffer s&1 free for reuse
    }

    // ---- epilogue: RED.ADD the per-block 64x64 partial into out (pre-decayed) ----
    float* outp = out + ((size_t)h << 12);
#pragma unroll
    for (int mt = 0; mt < 4; ++mt)
#pragma unroll
        for (int n2 = 0; n2 < 2; ++n2) {
            const int row = 16 * mt + r2;
            const int col = nb + 8 * n2 + 2 * c2;
            atomicAdd(outp + (size_t)row * DV_ + col,       cacc[mt][n2][0]);
            atomicAdd(outp + (size_t)row * DV_ + col + 1,   cacc[mt][n2][1]);
            atomicAdd(outp + (size_t)(row + 8) * DV_ + col,     cacc[mt][n2][2]);
            atomicAdd(outp + (size_t)(row + 8) * DV_ + col + 1, cacc[mt][n2][3]);
        }
}

__global__ void l1w_init_kernel(const float* __restrict__ memory,
                                float* __restrict__ out) {
    const int e4 = blockIdx.x * blockDim.x + threadIdx.x;  // 0..16383 float4
    float4 m = ((const float4*)memory)[e4];
    m.x *= DECAY_; m.y *= DECAY_; m.z *= DECAY_; m.w *= DECAY_;
    ((float4*)out)[e4] = m;
}

extern "C" void kernel_launch(void* const* d_in, const int* in_sizes, int n_in,
                              void* d_out, int out_size) {
    const float* memory = (const float*)d_in[0];   // (16,64,64)
    const float* keys   = (const float*)d_in[1];   // (4,4096,16,64)
    const float* values = (const float*)d_in[2];   // (4,4096,16,64)
    const float* ws     = (const float*)d_in[3];   // (4,4096)
    float* out = (float*)d_out;                    // (16,64,64)

    cudaFuncSetAttribute(l1w_main_kernel,
                         cudaFuncAttributeMaxDynamicSharedMemorySize,
                         2 * BUFB_);

    l1w_init_kernel<<<128, 128>>>(memory, out);
    l1w_main_kernel<<<NBLK_, 128, 2 * BUFB_>>>(keys, values, ws, out);
}